// round 15
// baseline (speedup 1.0000x reference)
#include <cuda_runtime.h>
#include <cstdint>

// ---------------------------------------------------------------------------
// Multi-level dense 3x3x3 conv, C_in=C_out=16, B=2, SAME zero padding.
// f32x2-packed version: even/odd cin pairs ride in one 64-bit register and
// one fma.rn.f32x2 instruction (2x FFMA throughput, 2x fewer LDS).
// ---------------------------------------------------------------------------

typedef unsigned long long u64;

constexpr int NLEV  = 16;
constexpr int NTOT  = 1846083;           // sum of R^3 over all levels
constexpr int XH    = 18;                // x extent with halo
constexpr int YH    = 18;                // y extent with halo
constexpr int PLANE = YH * XH * 16;      // floats per z-plane in smem = 5184
constexpr int WSZ   = 27 * 16 * 16;      // weights per level = 6912 floats
constexpr int SMEM_FLOATS = WSZ + 16 + 3 * PLANE;   // 22480 floats = 89920 B
constexpr int TZ    = 8;                 // z-slab per block

__constant__ int c_R[NLEV]    = {16,18,20,22,25,27,30,34,38,42,47,52,58,64,72,80};
__constant__ int c_off[NLEV]  = {0,4096,9928,17928,28576,44201,63884,90884,
                                 130188,185060,259148,362971,503579,698691,
                                 960835,1334083};
// cumulative tile starts per level (tiles = 2 * ntx^2 * ntz)
__constant__ int c_ts[NLEV+1] = {0,4,28,52,76,108,140,172,262,352,460,568,
                                 792,1048,1304,1754,2254};
__constant__ int c_ntx[NLEV]  = {1,2,2,2,2,2,2,3,3,3,3,4,4,4,5,5};
__constant__ int c_ntz[NLEV]  = {2,3,3,3,4,4,4,5,5,6,6,7,8,8,9,10};

__device__ __forceinline__ void fma2(u64& d, u64 a, u64 b) {
    asm("fma.rn.f32x2 %0, %1, %2, %0;" : "+l"(d) : "l"(a), "l"(b));
}

// Load global z-plane gz (with x/y halo, zero padded) into smem slot gz mod 3.
// Smem plane layout is the NATURAL [y][x][cin] layout (cin innermost), so the
// stage is a straight float4 copy and a cin-pair is a contiguous LDS.64.
__device__ __forceinline__ void load_plane(float* p_s, const float* __restrict__ inB,
                                           int R, int x0, int y0, int gz)
{
    float* dst = p_s + (((gz % 3) + 3) % 3) * PLANE;
    const int tid = threadIdx.x;
    if (gz < 0 || gz >= R) {
        float4 z4 = make_float4(0.f, 0.f, 0.f, 0.f);
        for (int u = tid; u < PLANE / 4; u += 256)
            reinterpret_cast<float4*>(dst)[u] = z4;
        return;
    }
    const float* src = inB + (size_t)gz * R * R * 16;
    // 18*18 voxels * 4 float4 chunks of the 16 channels
    for (int u = tid; u < YH * XH * 4; u += 256) {
        const int c4 = u & 3;
        const int v  = u >> 2;
        const int i  = v % XH;
        const int j  = v / XH;
        const int gx = x0 - 1 + i;
        const int gy = y0 - 1 + j;
        float4 val = make_float4(0.f, 0.f, 0.f, 0.f);
        if ((unsigned)gx < (unsigned)R && (unsigned)gy < (unsigned)R)
            val = *reinterpret_cast<const float4*>(
                      src + ((size_t)gy * R + gx) * 16 + c4 * 4);
        reinterpret_cast<float4*>(dst + (j * XH + i) * 16)[c4] = val;
    }
}

extern "C" __global__ void __launch_bounds__(256, 2)
conv_all_levels(const float* __restrict__ input,
                const float* __restrict__ weight,
                const float* __restrict__ bias,
                float* __restrict__ out)
{
    extern __shared__ float smem[];
    float* w_f = smem;                 // weight pairs: [27][8][16] float2
    float* b_s = smem + WSZ;           // [16]
    float* p_s = smem + WSZ + 16;      // 3 planes, [y][x][cin]
    const u64* wp = reinterpret_cast<const u64*>(w_f);

    const int tid = threadIdx.x;

    // ---- decode block -> (level, batch, tile) ----
    int l = 0;
    const int bId = blockIdx.x;
    while (bId >= c_ts[l + 1]) ++l;
    int t = bId - c_ts[l];
    const int R     = c_R[l];
    const int ntx   = c_ntx[l];
    const int ntz   = c_ntz[l];
    const int nxy   = ntx * ntx;
    const int per_b = nxy * ntz;
    const int b   = t / per_b;  t -= b * per_b;
    const int tz  = t / nxy;    t -= tz * nxy;
    const int tyi = t / ntx;
    const int txi = t - tyi * ntx;
    const int x0 = txi * 16, y0 = tyi * 16, z0 = tz * TZ;

    const float* inB  = input + ((size_t)b * NTOT + c_off[l]) * 16;
    float*       outB = out   + ((size_t)b * NTOT + c_off[l]) * 16;

    // ---- stage weights as cin-pair float2: wp[k][cp][co] = (w[k][2cp][co], w[k][2cp+1][co])
    const float* wg = weight + l * WSZ;
    for (int u = tid; u < 27 * 8 * 16; u += 256) {
        const int co = u & 15;
        const int cp = (u >> 4) & 7;
        const int k  = u >> 7;
        float2 v;
        v.x = wg[k * 256 + (2 * cp)     * 16 + co];
        v.y = wg[k * 256 + (2 * cp + 1) * 16 + co];
        reinterpret_cast<float2*>(w_f)[u] = v;
    }
    if (tid < 16) b_s[tid] = bias[l * 16 + tid];

    // ---- preload planes z0-1, z0 ----
    load_plane(p_s, inB, R, x0, y0, z0 - 1);
    load_plane(p_s, inB, R, x0, y0, z0);
    __syncthreads();

    // thread = (cout, local x); accumulates a 16-long y strip (f32x2 = even/odd cin).
    const int  co   = tid & 15;
    const int  xl   = tid >> 4;
    const bool warp_on = (x0 + 2 * (tid >> 5)) < R;  // whole-warp x-padding skip
    const bool x_ok    = (x0 + xl) < R;
    const float fbias  = b_s[co];
    const int zend = min(z0 + TZ, R);
    const int ymax = min(16, R - y0);

    for (int z = z0; z < zend; ++z) {
        load_plane(p_s, inB, R, x0, y0, z + 1);
        __syncthreads();

        u64 acc[16];
        #pragma unroll
        for (int y = 0; y < 16; ++y) acc[y] = 0ull;

        if (warp_on) {
            #pragma unroll 1
            for (int dz = 0; dz < 3; ++dz) {
                const float* pl = p_s + ((((z - 1 + dz) % 3) + 3) % 3) * PLANE;
                #pragma unroll 1
                for (int dx = 0; dx < 3; ++dx) {
                    // cin-pair column: float2 units; voxel (j, xl+dx) at
                    // float2-offset (j*XH + xl+dx)*8 + cp
                    const u64* col = reinterpret_cast<const u64*>(pl) + (xl + dx) * 8;
                    const u64* wk  = wp + (dz * 9 + dx) * 128 + co;  // + dy*3*128 + cp*16
                    #pragma unroll 1
                    for (int cp = 0; cp < 8; ++cp) {
                        u64 r2[18];
                        #pragma unroll
                        for (int j = 0; j < 18; ++j)
                            r2[j] = col[j * (XH * 8) + cp];
                        #pragma unroll
                        for (int dy = 0; dy < 3; ++dy) {
                            const u64 w2 = wk[dy * 384 + cp * 16];
                            #pragma unroll
                            for (int y = 0; y < 16; ++y)
                                fma2(acc[y], r2[y + dy], w2);
                        }
                    }
                }
            }
        }
        __syncthreads();   // protect plane slot reuse by next iteration's load

        if (x_ok) {
            float* o = outB + ((size_t)z * R * R + (size_t)y0 * R + (x0 + xl)) * 16 + co;
            for (int y = 0; y < ymax; ++y) {
                float2 v = *reinterpret_cast<float2*>(&acc[y]);
                o[(size_t)y * R * 16] = v.x + v.y + fbias;  // warp-coalesced store
            }
        }
    }
}

extern "C" void kernel_launch(void* const* d_in, const int* in_sizes, int n_in,
                              void* d_out, int out_size)
{
    const float* input  = (const float*)d_in[0];
    const float* weight = (const float*)d_in[1];
    const float* bias   = (const float*)d_in[2];
    float* out = (float*)d_out;

    cudaFuncSetAttribute(conv_all_levels,
                         cudaFuncAttributeMaxDynamicSharedMemorySize,
                         SMEM_FLOATS * (int)sizeof(float));
    conv_all_levels<<<2254, 256, SMEM_FLOATS * sizeof(float)>>>(input, weight, bias, out);
}

// round 16
// speedup vs baseline: 4.8090x; 4.8090x over previous
#include <cuda_runtime.h>
#include <cuda_fp16.h>
#include <cstdint>

// ---------------------------------------------------------------------------
// Multi-level dense 3x3x3 conv, C_in=C_out=16, B=2, SAME zero padding.
// Tensor-core version: 27 shift-GEMMs via mma.sync.m16n8k16 (fp16 x fp16 -> fp32).
// Input planes staged in smem as fp16 [y_halo][x_halo][cin]; a voxel row is
// 32 contiguous bytes, so ldmatrix.x4 with shifted row addresses materializes
// the A-tile for any (dy,dx) offset directly (halo zeros = SAME padding).
// ---------------------------------------------------------------------------

constexpr int NLEV   = 16;
constexpr int NTOT   = 1846083;          // sum of R^3 over all levels
constexpr int XH     = 18;               // x extent with halo
constexpr int YH     = 18;               // y extent with halo
constexpr int PLANE_H = YH * XH * 16;    // halves per z-plane = 5184 (10368 B)
constexpr int WH     = 27 * 16 * 16;     // weight halves per level = 6912
constexpr int TZ     = 8;                // z-slab per block

__constant__ int c_R[NLEV]    = {16,18,20,22,25,27,30,34,38,42,47,52,58,64,72,80};
__constant__ int c_off[NLEV]  = {0,4096,9928,17928,28576,44201,63884,90884,
                                 130188,185060,259148,362971,503579,698691,
                                 960835,1334083};
// cumulative tile starts per level (tiles = 2 * ntx^2 * ntz)
__constant__ int c_ts[NLEV+1] = {0,4,28,52,76,108,140,172,262,352,460,568,
                                 792,1048,1304,1754,2254};
__constant__ int c_ntx[NLEV]  = {1,2,2,2,2,2,2,3,3,3,3,4,4,4,5,5};
__constant__ int c_ntz[NLEV]  = {2,3,3,3,4,4,4,5,5,6,6,7,8,8,9,10};

__device__ __forceinline__ uint32_t smem_u32(const void* p) {
    return (uint32_t)__cvta_generic_to_shared(p);
}

__device__ __forceinline__ void ldsm_x4(uint32_t& r0, uint32_t& r1,
                                        uint32_t& r2, uint32_t& r3, uint32_t addr) {
    asm volatile("ldmatrix.sync.aligned.m8n8.x4.shared.b16 {%0,%1,%2,%3}, [%4];\n"
                 : "=r"(r0), "=r"(r1), "=r"(r2), "=r"(r3) : "r"(addr));
}

__device__ __forceinline__ void ldsm_x4_trans(uint32_t& r0, uint32_t& r1,
                                              uint32_t& r2, uint32_t& r3, uint32_t addr) {
    asm volatile("ldmatrix.sync.aligned.m8n8.x4.trans.shared.b16 {%0,%1,%2,%3}, [%4];\n"
                 : "=r"(r0), "=r"(r1), "=r"(r2), "=r"(r3) : "r"(addr));
}

__device__ __forceinline__ void mma16816(float* d, uint32_t a0, uint32_t a1,
                                         uint32_t a2, uint32_t a3,
                                         uint32_t b0, uint32_t b1) {
    asm volatile(
        "mma.sync.aligned.m16n8k16.row.col.f32.f16.f16.f32 "
        "{%0,%1,%2,%3}, {%4,%5,%6,%7}, {%8,%9}, {%0,%1,%2,%3};\n"
        : "+f"(d[0]), "+f"(d[1]), "+f"(d[2]), "+f"(d[3])
        : "r"(a0), "r"(a1), "r"(a2), "r"(a3), "r"(b0), "r"(b1));
}

// Load global z-plane gz (with x/y halo, zero padded) into fp16 smem slot gz mod 3.
__device__ __forceinline__ void load_plane(__half* p_s, const float* __restrict__ inB,
                                           int R, int x0, int y0, int gz)
{
    __half* dst = p_s + ((gz + 3) % 3) * PLANE_H;   // gz >= -1 always
    const int tid = threadIdx.x;
    if (gz < 0 || gz >= R) {
        uint4 z4 = make_uint4(0, 0, 0, 0);
        for (int u = tid; u < PLANE_H / 8; u += 256)
            reinterpret_cast<uint4*>(dst)[u] = z4;
        return;
    }
    const float* src = inB + (size_t)gz * R * R * 16;
    for (int u = tid; u < YH * XH * 4; u += 256) {
        const int c4 = u & 3;
        const int v  = u >> 2;
        const int i  = v % XH;
        const int j  = v / XH;
        const int gx = x0 - 1 + i;
        const int gy = y0 - 1 + j;
        float4 val = make_float4(0.f, 0.f, 0.f, 0.f);
        if ((unsigned)gx < (unsigned)R && (unsigned)gy < (unsigned)R)
            val = *reinterpret_cast<const float4*>(
                      src + ((size_t)gy * R + gx) * 16 + c4 * 4);
        __half2 h01 = __floats2half2_rn(val.x, val.y);
        __half2 h23 = __floats2half2_rn(val.z, val.w);
        uint2 pk;
        pk.x = *reinterpret_cast<uint32_t*>(&h01);
        pk.y = *reinterpret_cast<uint32_t*>(&h23);
        *reinterpret_cast<uint2*>(dst + (j * XH + i) * 16 + c4 * 4) = pk;
    }
}

extern "C" __global__ void __launch_bounds__(256)
conv_all_levels(const float* __restrict__ input,
                const float* __restrict__ weight,
                const float* __restrict__ bias,
                float* __restrict__ out)
{
    __shared__ __half w_s[WH];          // fp16 weights [27][ci][co]
    __shared__ float  b_s[16];
    __shared__ __half p_s[3 * PLANE_H]; // 3 z-planes, [y_halo][x_halo][cin]

    const int tid = threadIdx.x;

    // ---- decode block -> (level, batch, tile) ----
    int l = 0;
    const int bId = blockIdx.x;
    while (bId >= c_ts[l + 1]) ++l;
    int t = bId - c_ts[l];
    const int R     = c_R[l];
    const int ntx   = c_ntx[l];
    const int ntz   = c_ntz[l];
    const int nxy   = ntx * ntx;
    const int per_b = nxy * ntz;
    const int b   = t / per_b;  t -= b * per_b;
    const int tz  = t / nxy;    t -= tz * nxy;
    const int tyi = t / ntx;
    const int txi = t - tyi * ntx;
    const int x0 = txi * 16, y0 = tyi * 16, z0 = tz * TZ;

    const float* inB  = input + ((size_t)b * NTOT + c_off[l]) * 16;
    float*       outB = out   + ((size_t)b * NTOT + c_off[l]) * 16;

    // ---- stage fp16 weights + fp32 bias ----
    const float* wg = weight + l * WH;
    for (int u = tid; u < WH; u += 256) w_s[u] = __float2half(wg[u]);
    if (tid < 16) b_s[tid] = bias[l * 16 + tid];

    // ---- preload planes z0-1, z0 ----
    load_plane(p_s, inB, R, x0, y0, z0 - 1);
    load_plane(p_s, inB, R, x0, y0, z0);
    __syncthreads();

    const int lane = tid & 31;
    const int wid  = tid >> 5;
    const int yl   = wid * 2;                       // local y of warp's first row
    // ldmatrix per-lane address component: row (l&15)*32B + k/n-half (l>>4)*16B
    const uint32_t lane_off = (uint32_t)((lane & 15) * 32 + (lane >> 4) * 16);
    const uint32_t wbase = smem_u32(w_s);
    const uint32_t pbase = smem_u32(p_s);

    const bool warp_act = (y0 + yl) < R;
    const int  zend = min(z0 + TZ, R);

    // per-thread bias pairs for the two n-halves: co = (lane&3)*2 + h*8
    const int co0 = (lane & 3) * 2;
    float2 bias_h[2];
    bias_h[0] = make_float2(b_s[co0],     b_s[co0 + 1]);
    bias_h[1] = make_float2(b_s[co0 + 8], b_s[co0 + 9]);

    for (int z = z0; z < zend; ++z) {
        load_plane(p_s, inB, R, x0, y0, z + 1);
        __syncthreads();

        float d[2][8];
        #pragma unroll
        for (int i = 0; i < 16; ++i) d[i >> 3][i & 7] = 0.f;

        if (warp_act) {
            #pragma unroll
            for (int dz = 0; dz < 3; ++dz) {
                const uint32_t pb = pbase + (uint32_t)(((z - 1 + dz + 3) % 3) * PLANE_H * 2);
                #pragma unroll
                for (int dy = 0; dy < 3; ++dy) {
                    #pragma unroll
                    for (int dx = 0; dx < 3; ++dx) {
                        const int k = dz * 9 + dy * 3 + dx;
                        uint32_t b0, b1, b2, b3;
                        ldsm_x4_trans(b0, b1, b2, b3, wbase + (uint32_t)(k * 512) + lane_off);
                        #pragma unroll
                        for (int tt = 0; tt < 2; ++tt) {
                            // A tile: rows = voxels x=0..15 at halo (yl+tt+dy, x+dx)
                            const uint32_t aaddr =
                                pb + (uint32_t)(((yl + tt + dy) * XH + dx) * 32) + lane_off;
                            uint32_t a0, a1, a2, a3;
                            ldsm_x4(a0, a1, a2, a3, aaddr);
                            mma16816(d[tt],     a0, a1, a2, a3, b0, b1);
                            mma16816(d[tt] + 4, a0, a1, a2, a3, b2, b3);
                        }
                    }
                }
            }
        }
        __syncthreads();   // protect plane slot reuse by next iteration's load

        if (warp_act) {
            const int xA = x0 + (lane >> 2);       // rows l/4 and l/4+8 of D
            const int xB = xA + 8;
            #pragma unroll
            for (int tt = 0; tt < 2; ++tt) {
                const int yg = y0 + yl + tt;
                if (yg >= R) break;
                float* orow = outB + ((size_t)z * R * R + (size_t)yg * R) * 16;
                #pragma unroll
                for (int h = 0; h < 2; ++h) {
                    const int co = co0 + h * 8;
                    if (xA < R) {
                        float2 v = make_float2(d[tt][h * 4 + 0] + bias_h[h].x,
                                               d[tt][h * 4 + 1] + bias_h[h].y);
                        *reinterpret_cast<float2*>(orow + (size_t)xA * 16 + co) = v;
                    }
                    if (xB < R) {
                        float2 v = make_float2(d[tt][h * 4 + 2] + bias_h[h].x,
                                               d[tt][h * 4 + 3] + bias_h[h].y);
                        *reinterpret_cast<float2*>(orow + (size_t)xB * 16 + co) = v;
                    }
                }
            }
        }
    }
}

extern "C" void kernel_launch(void* const* d_in, const int* in_sizes, int n_in,
                              void* d_out, int out_size)
{
    const float* input  = (const float*)d_in[0];
    const float* weight = (const float*)d_in[1];
    const float* bias   = (const float*)d_in[2];
    float* out = (float*)d_out;

    conv_all_levels<<<2254, 256>>>(input, weight, bias, out);
}